// round 16
// baseline (speedup 1.0000x reference)
#include <cuda_runtime.h>
#include <cuda_fp16.h>
#include <cstdint>

// Problem constants
#define BB 4
#define TT 512
#define EE 1024
#define HH 16
#define DK 64
#define BT (BB*TT)          // 2048

// ---------------------------------------------------------------------------
// Device scratch
// ---------------------------------------------------------------------------
__device__ __half g_qh16[BB*HH*TT*DK];       // head-major qlin (fp16)
__device__ __half g_vh16[BB*HH*TT*DK];       // head-major vlin (fp16)
__device__ __half g_x16[BT*EE];              // fp16(x)
__device__ __half g_a16[BT*EE];              // fp16(attn out)
__device__ __half g_w16[3][EE*EE];           // W^T fp16: [n][k]  0=Wq 1=Wv 2=Wo

__device__ __forceinline__ uint32_t smem_u32(const void* p) {
    uint32_t a;
    asm("{ .reg .u64 t; cvta.to.shared.u64 t, %1; cvt.u32.u64 %0, t; }"
        : "=r"(a) : "l"(p));
    return a;
}

__device__ __forceinline__ void cp16(uint32_t dst, const void* src) {
    asm volatile("cp.async.cg.shared.global [%0], [%1], 16;"
                 :: "r"(dst), "l"(src) : "memory");
}

#define LDSM_X4(r0,r1,r2,r3,addr) \
    asm volatile("ldmatrix.sync.aligned.m8n8.x4.shared.b16 {%0,%1,%2,%3}, [%4];" \
                 : "=r"(r0), "=r"(r1), "=r"(r2), "=r"(r3) : "r"(addr))
#define MMA_F16(c, a, b) \
    asm volatile("mma.sync.aligned.m16n8k16.row.col.f32.f16.f16.f32 " \
                 "{%0,%1,%2,%3}, {%4,%5,%6,%7}, {%8,%9}, {%0,%1,%2,%3};" \
                 : "+f"((c)[0]), "+f"((c)[1]), "+f"((c)[2]), "+f"((c)[3]) \
                 : "r"((a)[0]), "r"((a)[1]), "r"((a)[2]), "r"((a)[3]), \
                   "r"((b)[0]), "r"((b)[1]))

// smem: 2 tiles of 128 rows x 80 B (A, B), 2-stage
#define ROWP   80
#define TILEB  (128*ROWP)            // 10240
#define OFF_A  0
#define OFF_B  (1*TILEB)
#define BUFB   (2*TILEB)             // 20480
#define SMEM_BYTES (2*BUFB)          // 40960

#define NKT 32                       // 32 K-tiles of 32 -> K = 1024

// ---------------------------------------------------------------------------
// Convert fp32 x -> fp16
// ---------------------------------------------------------------------------
__global__ __launch_bounds__(256) void split_src(const float* __restrict__ src)
{
    int i = (blockIdx.x * 256 + threadIdx.x) * 4;
    float4 v = *(const float4*)(src + i);
    __half h[4];
    h[0] = __float2half(v.x); h[1] = __float2half(v.y);
    h[2] = __float2half(v.z); h[3] = __float2half(v.w);
    *(uint2*)(g_x16 + i) = *(uint2*)h;
}

// ---------------------------------------------------------------------------
// Transpose weights to fp16: g_w16[z][n][k] = fp16(W_z[k][n])
// grid (32, 32, 3), block (32, 8)
// ---------------------------------------------------------------------------
__global__ void split_w(const float* __restrict__ Wq, const float* __restrict__ Wv,
                        const float* __restrict__ Wo)
{
    __shared__ float tile[32][33];
    const int z = blockIdx.z;
    const float* W = z == 0 ? Wq : (z == 1 ? Wv : Wo);
    const int n0 = blockIdx.x * 32;
    const int k0 = blockIdx.y * 32;
    const int tx = threadIdx.x, ty = threadIdx.y;

    #pragma unroll
    for (int i = 0; i < 4; i++)
        tile[ty + 8*i][tx] = W[(size_t)(k0 + ty + 8*i)*EE + n0 + tx];
    __syncthreads();
    #pragma unroll
    for (int i = 0; i < 4; i++) {
        int r = ty + 8*i;
        g_w16[z][(size_t)(n0 + r)*EE + k0 + tx] = __float2half(tile[tx][r]);
    }
}

// ---------------------------------------------------------------------------
// Single-pass fp16 tensor-core GEMM via mma.sync (fp32 accumulate).
// CTA 128x128, KT=32, 8 warps (2m x 4n), 2-stage single-sync pipeline.
// mode 0: out scattered head-major fp16 to g_qh16/g_vh16 (z: 0=q,1=v)
// mode 1: out fp32 row-major (d_out)
// ---------------------------------------------------------------------------
__global__ __launch_bounds__(256, 2) void mma_gemm(
    int wbase, const float* __restrict__ bias0, const float* __restrict__ bias1,
    float* __restrict__ outp, int mode)
{
    extern __shared__ char smem[];
    const uint32_t sb = smem_u32(smem);
    const int tid = threadIdx.x;
    const int wid = tid >> 5;
    const int l   = tid & 31;
    const int wm  = wid & 1;
    const int wn  = wid >> 1;

    const int n0 = blockIdx.x * 128;
    const int m0 = blockIdx.y * 128;
    const int z  = blockIdx.z;
    const float* bias = z ? bias1 : bias0;

    const __half* Aa = mode ? g_a16 : g_x16;
    const __half* Bw = g_w16[wbase + z];

    const int gr  = tid >> 1;
    const int gs  = tid & 1;
    const size_t aoff = (size_t)(m0 + gr) * EE + gs * 16;
    const size_t boff = (size_t)(n0 + gr) * EE + gs * 16;
    const uint32_t srow = gr * ROWP + gs * 32;

    float acc[4][4][4] = {};

    auto load_tile = [&](int kt, int b) {
        const int kc = kt * 32;
        const uint32_t d = sb + b * BUFB + srow;
        cp16(d + OFF_A,       Aa + aoff + kc);
        cp16(d + OFF_A + 16,  Aa + aoff + kc + 8);
        cp16(d + OFF_B,       Bw + boff + kc);
        cp16(d + OFF_B + 16,  Bw + boff + kc + 8);
        asm volatile("cp.async.commit_group;" ::: "memory");
    };

    const uint32_t aBase  = (uint32_t)((wm*64 + (l & 15)) * ROWP + (l & 16));
    const uint32_t bBase4 = (uint32_t)((wn*32 + (l & 7) + ((l & 16) >> 1)) * ROWP
                                       + ((l & 8) << 1));

    load_tile(0, 0);

    for (int kt = 0; kt < NKT; kt++) {
        asm volatile("cp.async.wait_group 0;" ::: "memory");
        __syncthreads();
        if (kt + 1 < NKT) load_tile(kt + 1, (kt + 1) & 1);

        const uint32_t bufb = sb + (kt & 1) * BUFB;
        #pragma unroll
        for (int ks = 0; ks < 2; ks++) {
            const uint32_t kb = ks * 32;
            uint32_t bh[4][2], ah[4][4];
            LDSM_X4(bh[0][0], bh[0][1], bh[1][0], bh[1][1],
                    bufb + OFF_B + bBase4 + kb);
            LDSM_X4(bh[2][0], bh[2][1], bh[3][0], bh[3][1],
                    bufb + OFF_B + bBase4 + 16*ROWP + kb);
            #pragma unroll
            for (int mf = 0; mf < 4; mf++)
                LDSM_X4(ah[mf][0], ah[mf][1], ah[mf][2], ah[mf][3],
                        bufb + OFF_A + aBase + mf*16*ROWP + kb);
            #pragma unroll
            for (int mf = 0; mf < 4; mf++)
                #pragma unroll
                for (int nf = 0; nf < 4; nf++)
                    MMA_F16(acc[mf][nf], ah[mf], bh[nf]);
        }
    }

    // Epilogue
    const int g   = l >> 2;
    const int tig = l & 3;
    #pragma unroll
    for (int mf = 0; mf < 4; mf++) {
        const int m = m0 + wm*64 + mf*16 + g;
        const int b = m >> 9;
        const int t = m & 511;
        #pragma unroll
        for (int nf = 0; nf < 4; nf++) {
            const int n = n0 + wn*32 + nf*8 + tig*2;
            float v0 = acc[mf][nf][0] + bias[n];
            float v1 = acc[mf][nf][1] + bias[n+1];
            float v2 = acc[mf][nf][2] + bias[n];
            float v3 = acc[mf][nf][3] + bias[n+1];
            if (mode == 0) {
                __half* dst = z ? g_vh16 : g_qh16;
                int h0 = n & (HH-1),   d0 = n >> 4;
                int h1 = (n+1)&(HH-1), d1 = (n+1) >> 4;
                dst[((b*HH + h0)*TT + t)*DK + d0]     = __float2half(v0);
                dst[((b*HH + h1)*TT + t)*DK + d1]     = __float2half(v1);
                dst[((b*HH + h0)*TT + t + 8)*DK + d0] = __float2half(v2);
                dst[((b*HH + h1)*TT + t + 8)*DK + d1] = __float2half(v3);
            } else {
                outp[(size_t)m*EE + n]       = v0;
                outp[(size_t)m*EE + n + 1]   = v1;
                outp[(size_t)(m+8)*EE + n]   = v2;
                outp[(size_t)(m+8)*EE + n+1] = v3;
            }
        }
    }
}

// ---------------------------------------------------------------------------
// Windowed attention with fp16 K/V smem tiles (fp32 math).
// Pitch 72 halves = 9 x 16B segments: score phase (r+i)%8 and V phase
// (r+dg)%8 are octet permutations per quarter-warp -> conflict-free LDS.128.
// grid (16, 64), 256 threads
// ---------------------------------------------------------------------------
__global__ __launch_bounds__(256) void attn_kernel()
{
    __shared__ __align__(16) __half Ks[96][72];
    __shared__ float Ps[32][68];

    const int bh = blockIdx.y;
    const int t0 = blockIdx.x * 32;
    const __half* qb = g_qh16 + bh*TT*DK;
    const __half* vb = g_vh16 + bh*TT*DK;

    // ---- load K tile (clamped window), 16B chunks ----
    for (int idx = threadIdx.x; idx < 96*8; idx += 256) {
        int r = idx >> 3;
        int c = idx & 7;             // 16B chunk = 8 halves
        int src = t0 - 32 + r;
        src = src < 0 ? 0 : (src > TT-1 ? TT-1 : src);
        *(uint4*)&Ks[r][c*8] = *(const uint4*)(qb + src*DK + c*8);
    }
    __syncthreads();

    const int t_l = threadIdx.x >> 3;
    const int wg  = threadIdx.x & 7;
    const float scale = 1.0f / 32.0f;

    // ---- cache Q row in fp32 registers ----
    float q[64];
    const int qrow = 32 + t_l;
    #pragma unroll
    for (int i = 0; i < 8; i++) {
        uint4 kv = *(const uint4*)&Ks[qrow][i*8];
        const __half2* hp = (const __half2*)&kv;
        #pragma unroll
        for (int p = 0; p < 4; p++) {
            float2 f = __half22float2(hp[p]);
            q[i*8 + 2*p]     = f.x;
            q[i*8 + 2*p + 1] = f.y;
        }
    }

    // ---- scores: thread owns w = wg + 8*j ----
    float acc[8];
    #pragma unroll
    for (int j = 0; j < 8; j++) {
        const int r = t_l + wg + 8*j;
        float a = 0.f;
        #pragma unroll
        for (int i = 0; i < 8; i++) {
            uint4 kv = *(const uint4*)&Ks[r][i*8];
            const __half2* hp = (const __half2*)&kv;
            #pragma unroll
            for (int p = 0; p < 4; p++) {
                float2 f = __half22float2(hp[p]);
                a = fmaf(q[i*8 + 2*p],     f.x, a);
                a = fmaf(q[i*8 + 2*p + 1], f.y, a);
            }
        }
        acc[j] = a;
    }

    // ---- softmax over the 8-lane group ----
    float m = -1e30f;
    #pragma unroll
    for (int j = 0; j < 8; j++) { acc[j] *= scale; m = fmaxf(m, acc[j]); }
    #pragma unroll
    for (int off = 1; off < 8; off <<= 1)
        m = fmaxf(m, __shfl_xor_sync(0xffffffffu, m, off));
    float s = 0.f, p[8];
    #pragma unroll
    for (int j = 0; j < 8; j++) { p[j] = __expf(acc[j] - m); s += p[j]; }
    #pragma unroll
    for (int off = 1; off < 8; off <<= 1)
        s += __shfl_xor_sync(0xffffffffu, s, off);
    float inv = 1.0f / s;
    #pragma unroll
    for (int j = 0; j < 8; j++)
        Ps[t_l][wg + 8*j] = p[j] * inv;

    __syncthreads();

    // ---- load V tile over K buffer ----
    for (int idx = threadIdx.x; idx < 96*8; idx += 256) {
        int r = idx >> 3;
        int c = idx & 7;
        int src = t0 - 32 + r;
        src = src < 0 ? 0 : (src > TT-1 ? TT-1 : src);
        *(uint4*)&Ks[r][c*8] = *(const uint4*)(vb + src*DK + c*8);
    }
    __syncthreads();

    // ---- output: thread owns d = 8dg .. 8dg+7 (one 16B load per w) ----
    const int dg = wg;
    float ao[8] = {};
    #pragma unroll 8
    for (int w = 0; w < 64; w++) {
        float pw = Ps[t_l][w];
        const int r = t_l + w;
        uint4 kv = *(const uint4*)&Ks[r][dg*8];
        const __half2* hp = (const __half2*)&kv;
        #pragma unroll
        for (int pp = 0; pp < 4; pp++) {
            float2 f = __half22float2(hp[pp]);
            ao[2*pp]     = fmaf(pw, f.x, ao[2*pp]);
            ao[2*pp + 1] = fmaf(pw, f.y, ao[2*pp + 1]);
        }
    }

    // ---- fp16 epilogue: single 16B store ----
    const int b = bh >> 4, h = bh & 15;
    const int t = t0 + t_l;
    const int base = (b*TT + t)*EE + h*DK + dg*8;
    __half hh[8];
    #pragma unroll
    for (int i = 0; i < 8; i++) hh[i] = __float2half(ao[i]);
    *(uint4*)(g_a16 + base) = *(uint4*)hh;
}

// ---------------------------------------------------------------------------
// Inputs: 0:x 1:position_mask(unused) 2:Wq 3:bq 4:Wv 5:bv 6:Wo 7:bo
// ---------------------------------------------------------------------------
extern "C" void kernel_launch(void* const* d_in, const int* in_sizes, int n_in,
                              void* d_out, int out_size)
{
    const float* x  = (const float*)d_in[0];
    const float* Wq = (const float*)d_in[2];
    const float* bq = (const float*)d_in[3];
    const float* Wv = (const float*)d_in[4];
    const float* bv = (const float*)d_in[5];
    const float* Wo = (const float*)d_in[6];
    const float* bo = (const float*)d_in[7];
    float* out = (float*)d_out;

    cudaFuncSetAttribute(mma_gemm, cudaFuncAttributeMaxDynamicSharedMemorySize, SMEM_BYTES);

    split_src<<<BT*EE/1024, 256>>>(x);
    split_w<<<dim3(32, 32, 3), dim3(32, 8)>>>(Wq, Wv, Wo);
    mma_gemm<<<dim3(8, 16, 2), 256, SMEM_BYTES>>>(0, bq, bv, nullptr, 0);
    attn_kernel<<<dim3(16, 64), 256>>>();
    mma_gemm<<<dim3(8, 16, 1), 256, SMEM_BYTES>>>(2, bo, bo, out, 1);
}